// round 12
// baseline (speedup 1.0000x reference)
#include <cuda_runtime.h>
#include <cstdint>

#define NB 32
#define THREADS 800          // 24 consumer warps + 1 producer warp
#define CONS_T  768
#define NCONS   24
#define NWTOT   25
#define STAGES  3
#define SROWS   24           // rows (1KB each) per stage

// byte offsets into dynamic SMEM
#define OFF_IW2 0            // 32*1024 floats folded: IW + W[2p][a] + W[2p+1][b]
#define OFF_WH  131072       // W rows 64..255, stride 33 (6336 floats)
#define OFF_Z   156416       // 32 zero floats
#define OFF_H   156544       // 64-int histogram
#define OFF_F   156800       // flags
#define OFF_MB  156816       // 3 stages x (full,empty) mbarriers, 16B/stage
#define OFF_STG 157696       // 3 x 24KB x-stream ring (1KB-aligned)
#define SMEM_TOTAL (OFF_STG + STAGES * SROWS * 1024)   // 231424 B

__device__ int g_hist[64];
__device__ unsigned int g_ctr = 0;

static __device__ __forceinline__ uint32_t s2u(const void* p) {
    uint32_t r;
    asm("{ .reg .u64 t; cvta.to.shared.u64 t, %1; cvt.u32.u64 %0, t; }"
        : "=r"(r) : "l"(p));
    return r;
}
static __device__ __forceinline__ void mbar_init(uint32_t a, uint32_t cnt) {
    asm volatile("mbarrier.init.shared.b64 [%0], %1;" :: "r"(a), "r"(cnt) : "memory");
}
static __device__ __forceinline__ void mbar_arrive(uint32_t a) {
    asm volatile("mbarrier.arrive.shared.b64 _, [%0];" :: "r"(a) : "memory");
}
static __device__ __forceinline__ void mbar_expect_tx(uint32_t a, uint32_t bytes) {
    asm volatile("mbarrier.arrive.expect_tx.shared.b64 _, [%0], %1;"
                 :: "r"(a), "r"(bytes) : "memory");
}
static __device__ __forceinline__ void mbar_wait(uint32_t a, uint32_t parity) {
    asm volatile(
        "{\n\t.reg .pred P;\n\t"
        "W_%=:\n\t"
        "mbarrier.try_wait.parity.acquire.cta.shared::cta.b64 P, [%0], %1, 0x989680;\n\t"
        "@P bra.uni D_%=;\n\t"
        "bra.uni W_%=;\n\t"
        "D_%=:\n\t}"
        :: "r"(a), "r"(parity) : "memory");
}
static __device__ __forceinline__ void bulk_g2s(uint32_t dst, const void* src,
                                                uint32_t bytes, uint32_t bar) {
    asm volatile(
        "cp.async.bulk.shared::cluster.global.mbarrier::complete_tx::bytes "
        "[%0], [%1], %2, [%3];"
        :: "r"(dst), "l"(src), "r"(bytes), "r"(bar) : "memory");
}

// Exact floor(clip(v)*32): sat, FFMA.RZ(+2^23), mask. NaN -> 0 (matches ref).
__device__ __forceinline__ int bin_uni(float v) {
    float t = __saturatef(v);
    float y = __fmaf_rz(t, 32.0f, 8388608.0f);
    int k = __float_as_int(y) & 63;
    return k > 31 ? 31 : k;
}
__device__ __forceinline__ int bin_gen(float v, const float* __restrict__ e) {
    int c = 0;
#pragma unroll
    for (int k = 0; k < 33; ++k) c += (v >= e[k]) ? 1 : 0;
    c -= 1; c = c < 0 ? 0 : c;
    return c > 31 ? 31 : c;
}
__device__ __forceinline__ float warp_sum(float v) {
#pragma unroll
    for (int off = 16; off > 0; off >>= 1)
        v += __shfl_xor_sync(0xffffffffu, v, off);
    return v;
}

// ---------------- generic fallback (correctness only, pure gmem) ----------------
__device__ void slow_loop(const float* __restrict__ x, float* __restrict__ out,
                          const float* __restrict__ W, const float* __restrict__ IW,
                          const float* __restrict__ bins,
                          const int* __restrict__ pair_i, const int* __restrict__ pair_j,
                          unsigned* __restrict__ myIdx, int* __restrict__ sHist,
                          int lane, int P, int gw, int nw, int B, float icpt, bool uni)
{
    const unsigned char* ib = (const unsigned char*)myIdx;
    const int fa = 4 * lane, fc = 128 + 4 * lane;
    int mpi = (lane < P) ? pair_i[lane] : 0;
    int mpj = (lane < P) ? pair_j[lane] : 0;
    for (int row = gw; row < B; row += nw) {
        const float4* rp = (const float4*)(x + (size_t)row * 256);
        float4 a = rp[lane], c = rp[32 + lane];
        float vv[8] = {a.x, a.y, a.z, a.w, c.x, c.y, c.z, c.w};
        int id[8];
#pragma unroll
        for (int j = 0; j < 8; ++j) {
            int f = (j < 4) ? fa + j : fc + (j - 4);
            id[j] = uni ? bin_uni(vv[j]) : bin_gen(vv[j], bins + f * 33);
        }
        float s = 0.f;
#pragma unroll
        for (int j = 0; j < 8; ++j) {
            int f = (j < 4) ? fa + j : fc + (j - 4);
            s += __ldg(&W[f * 32 + id[j]]);
        }
        myIdx[lane]      = (unsigned)id[0] | ((unsigned)id[1] << 8)
                         | ((unsigned)id[2] << 16) | ((unsigned)id[3] << 24);
        myIdx[32 + lane] = (unsigned)id[4] | ((unsigned)id[5] << 8)
                         | ((unsigned)id[6] << 16) | ((unsigned)id[7] << 24);
        __syncwarp();
        if (lane < P) s += __ldg(&IW[lane * 1024 + ib[mpi] * 32 + ib[mpj]]);
        if (lane == 0)      atomicAdd(&sHist[id[0]], 1);
        else if (lane == 1) atomicAdd(&sHist[32 + id[1]], 1);
        s = warp_sum(s);
        if (lane == 0) out[row] = icpt + s;
    }
}

__global__ __launch_bounds__(THREADS, 1)
void fair_ebm_kernel(const float* __restrict__ x, const float* __restrict__ W,
                     const float* __restrict__ IW, const float* __restrict__ intercept,
                     const float* __restrict__ bins, const int* __restrict__ pair_i,
                     const int* __restrict__ pair_j, float* __restrict__ out,
                     int B, int P, int writeLoss)
{
    extern __shared__ char smem[];
    float* sIW2  = (float*)(smem + OFF_IW2);
    float* sWh   = (float*)(smem + OFF_WH);
    float* zeros = (float*)(smem + OFF_Z);
    int*   sHist = (int*)(smem + OFF_H);
    int*   sFlag = (int*)(smem + OFF_F);
    const uint32_t mb = s2u(smem + OFF_MB);
    float* sStg  = (float*)(smem + OFF_STG);

    const int tid  = threadIdx.x;
    const int lane = tid & 31;
    const int warp = tid >> 5;

    // contiguous row chunk per CTA
    const int chunk = (B + gridDim.x - 1) / gridDim.x;
    const int row0  = blockIdx.x * chunk;
    int rows = B - row0; if (rows > chunk) rows = chunk; if (rows < 0) rows = 0;
    const int nstages = (rows + SROWS - 1) / SROWS;

    if (tid == 0) {
        sFlag[0] = 1; sFlag[1] = 1;
        for (int s = 0; s < STAGES; ++s) {
            mbar_init(mb + s * 16,     1);       // full: 1 expect_tx arrival
            mbar_init(mb + s * 16 + 8, NCONS);   // empty: one per consumer warp
        }
    }
    if (tid < 64) sHist[tid] = 0;
    if (tid < 32) zeros[tid] = 0.0f;

    // ---- verify uniform bins + identity pairs (all 800 threads) ----
    {
        const float4* B4 = (const float4*)bins;
        bool bad = false;
        for (int i = tid; i < (256 * 33) / 4; i += THREADS) {
            float4 v = B4[i]; int e = i * 4;
            bad |= (v.x != (float)((e + 0) % 33) * 0.03125f);
            bad |= (v.y != (float)((e + 1) % 33) * 0.03125f);
            bad |= (v.z != (float)((e + 2) % 33) * 0.03125f);
            bad |= (v.w != (float)((e + 3) % 33) * 0.03125f);
        }
        if (bad) sFlag[0] = 0;
    }
    if (tid == 0 && P != 32) sFlag[1] = 0;
    if (tid < 32 && tid < P)
        if (pair_i[tid] != 2 * tid || pair_j[tid] != 2 * tid + 1) sFlag[1] = 0;
    __syncthreads();   // also publishes mbarrier inits before any TMA

    const bool  fast = (sFlag[0] != 0) && (sFlag[1] != 0);
    const float icpt = intercept[0];

    if (fast) {
        if (tid >= CONS_T) {
            // ---------------- producer (single thread) ----------------
            if (tid == CONS_T) {
                int st = 0, ph = 1;                 // phase 1: first empty-wait passes
                for (int it = 0; it < nstages; ++it) {
                    mbar_wait(mb + st * 16 + 8, (uint32_t)ph);
                    int base = it * SROWS;
                    int nv = rows - base; if (nv > SROWS) nv = SROWS;
                    uint32_t bytes = (uint32_t)nv * 1024u;
                    mbar_expect_tx(mb + st * 16, bytes);
                    bulk_g2s(s2u(sStg) + (uint32_t)st * (SROWS * 1024u),
                             x + (size_t)(row0 + base) * 256, bytes, mb + st * 16);
                    if (++st == STAGES) { st = 0; ph ^= 1; }
                }
            }
        } else {
            // ---------------- consumers: stage tables (TMA overlaps this) ----------------
            {
                const float4* W4 = (const float4*)W;
                for (int i = tid; i < 1536; i += CONS_T) {       // W rows 64..255
                    float4 v = W4[512 + i];
                    int f = i * 4;
                    float* d = sWh + (f >> 5) * 33 + (f & 31);   // (f&31) <= 28
                    d[0] = v.x; d[1] = v.y; d[2] = v.z; d[3] = v.w;
                }
                const float4* IW4 = (const float4*)IW;
                float4* D4 = (float4*)sIW2;
                for (int i = tid; i < 8192; i += CONS_T) {       // folded tables
                    float4 v = IW4[i];
                    int e = i * 4;
                    int p = e >> 10, a = (e >> 5) & 31, b = e & 31;
                    float wa = __ldg(&W[(2 * p) * 32 + a]);
                    float4 wb = __ldg((const float4*)&W[(2 * p + 1) * 32 + b]);
                    v.x += wa + wb.x; v.y += wa + wb.y;
                    v.z += wa + wb.z; v.w += wa + wb.w;
                    D4[i] = v;
                }
            }
            asm volatile("bar.sync 1, %0;" :: "n"(CONS_T) : "memory");

            // per-lane invariant lookup config (branch-free inner loop)
            const float *ub0, *ub1, *ub2, *ub3; int um, vm;
            if (lane < 16) {
                ub0 = sIW2 + (2 * lane) * 1024;
                ub1 = sIW2 + (2 * lane + 1) * 1024;
                ub2 = zeros; ub3 = zeros; um = 32; vm = 1;
            } else {
                int fr = 4 * lane - 64;
                ub0 = sWh + fr * 33;       ub1 = sWh + (fr + 2) * 33;
                ub2 = sWh + (fr + 1) * 33; ub3 = sWh + (fr + 3) * 33;
                um = 1; vm = 0;
            }
            const float* hb = sWh + (64 + 4 * lane) * 33;

            int st = 0, ph = 0;
            for (int it = 0; it < nstages; ++it) {
                mbar_wait(mb + st * 16, (uint32_t)ph);
                int base = it * SROWS;
                int nv = rows - base; if (nv > SROWS) nv = SROWS;
                if (warp < nv) {
                    const float* rd = sStg + st * (SROWS * 256) + warp * 256;
                    float4 a = *(const float4*)(rd + lane * 4);
                    float4 c = *(const float4*)(rd + 128 + lane * 4);
                    int p0 = bin_uni(a.x), p1 = bin_uni(a.y), p2 = bin_uni(a.z), p3 = bin_uni(a.w);
                    int p4 = bin_uni(c.x), p5 = bin_uni(c.y), p6 = bin_uni(c.z), p7 = bin_uni(c.w);
                    float s = ub0[p0 * um + p1 * vm] + ub1[p2 * um + p3 * vm]
                            + ub2[p1] + ub3[p3]
                            + hb[p4] + hb[33 + p5] + hb[66 + p6] + hb[99 + p7];
                    if (lane == 0)      atomicAdd(&sHist[p0], 1);
                    else if (lane == 1) atomicAdd(&sHist[32 + p1], 1);
                    s = warp_sum(s);
                    if (lane == 0) out[row0 + base + warp] = icpt + s;
                }
                __syncwarp();                        // all lanes' stage reads done
                if (lane == 0) mbar_arrive(mb + st * 16 + 8);
                if (++st == STAGES) { st = 0; ph ^= 1; }
            }
        }
    } else {
        unsigned* myIdx = (unsigned*)sStg + warp * 64;   // scratch in unused ring
        slow_loop(x, out, W, IW, bins, pair_i, pair_j, myIdx, sHist,
                  lane, P, blockIdx.x * NWTOT + warp, gridDim.x * NWTOT,
                  B, icpt, sFlag[0] != 0);
    }

    // ---- cross-block reduce + last-block finalize ----
    __syncthreads();
    if (tid < 64) atomicAdd(&g_hist[tid], sHist[tid]);
    __threadfence();
    __syncthreads();

    __shared__ unsigned ticket;
    if (tid == 0) ticket = atomicAdd(&g_ctr, 1u);
    __syncthreads();

    if (ticket == gridDim.x - 1) {
        if (tid < 64) sHist[tid] = atomicAdd(&g_hist[tid], 0);
        __syncthreads();
        if (tid < 32) {
            const double invB = 1.0 / (double)B;
            double vsum = 0.0;
#pragma unroll
            for (int s2i = 0; s2i < 2; ++s2i) {
                const int f = s2i ? 5 : 0;
                double wv  = (double)W[f * NB + tid];
                double cnt = (double)sHist[s2i * 32 + tid];
                double t1 = cnt * wv;
                double t2 = t1 * wv;
#pragma unroll
                for (int off = 16; off > 0; off >>= 1) {
                    t1 += __shfl_xor_sync(0xffffffffu, t1, off);
                    t2 += __shfl_xor_sync(0xffffffffu, t2, off);
                }
                double mean = t1 * invB;
                vsum += t2 * invB - mean * mean;
            }
            if (tid == 0) {
                if (writeLoss) out[B] = (float)(0.1 * vsum);
                g_ctr = 0;
            }
        }
        if (tid < 64) g_hist[tid] = 0;
        __threadfence();
    }
}

extern "C" void kernel_launch(void* const* d_in, const int* in_sizes, int n_in,
                              void* d_out, int out_size)
{
    const float* x         = (const float*)d_in[0];
    const float* W         = (const float*)d_in[1];
    const float* IW        = (const float*)d_in[2];
    const float* intercept = (const float*)d_in[3];
    const float* bins      = (const float*)d_in[4];
    const int*   pair_i    = (const int*)d_in[5];
    const int*   pair_j    = (const int*)d_in[6];
    float*       out       = (float*)d_out;

    const int B = in_sizes[0] / 256;
    const int P = in_sizes[2] / 1024;
    const int writeLoss = (out_size > B) ? 1 : 0;

    int dev = 0;
    cudaGetDevice(&dev);
    int sms = 148;
    cudaDeviceGetAttribute(&sms, cudaDevAttrMultiProcessorCount, dev);

    cudaFuncSetAttribute(fair_ebm_kernel,
                         cudaFuncAttributeMaxDynamicSharedMemorySize, SMEM_TOTAL);

    fair_ebm_kernel<<<sms, THREADS, SMEM_TOTAL>>>(x, W, IW, intercept, bins,
                                                  pair_i, pair_j, out, B, P, writeLoss);
}

// round 13
// speedup vs baseline: 1.0750x; 1.0750x over previous
#include <cuda_runtime.h>
#include <cstdint>

#define NB 32
#define THREADS 1024
#define NWARPS 32
#define MAXB 14            // rows per warp batch (RPW=14 for B=65536, grid=152)

__device__ int g_hist[64];
__device__ unsigned int g_ctr = 0;

// Exact floor(clip(v)*32): sat, FFMA.RZ(+2^23), mask. NaN -> 0 (matches ref).
__device__ __forceinline__ int bin_uni(float v) {
    float t = __saturatef(v);
    float y = __fmaf_rz(t, 32.0f, 8388608.0f);
    int k = __float_as_int(y) & 63;
    return k > 31 ? 31 : k;
}
__device__ __forceinline__ int bin_gen(float v, const float* __restrict__ e) {
    int c = 0;
#pragma unroll
    for (int k = 0; k < 33; ++k) c += (v >= e[k]) ? 1 : 0;
    c -= 1; c = c < 0 ? 0 : c;
    return c > 31 ? 31 : c;
}
__device__ __forceinline__ float warp_sum(float v) {
#pragma unroll
    for (int off = 16; off > 0; off >>= 1)
        v += __shfl_xor_sync(0xffffffffu, v, off);
    return v;
}

// ---------------- generic fallback (correctness only, pure gmem) ----------------
__device__ void slow_loop(const float* __restrict__ x, float* __restrict__ out,
                          const float* __restrict__ W, const float* __restrict__ IW,
                          const float* __restrict__ bins,
                          const int* __restrict__ pair_i, const int* __restrict__ pair_j,
                          unsigned* __restrict__ myIdx, int* __restrict__ sHist,
                          int lane, int P, int gw, int nw, int B, float icpt, bool uni)
{
    const unsigned char* ib = (const unsigned char*)myIdx;
    const int fa = 4 * lane, fc = 128 + 4 * lane;
    int mpi = (lane < P) ? pair_i[lane] : 0;
    int mpj = (lane < P) ? pair_j[lane] : 0;
    for (int row = gw; row < B; row += nw) {
        const float4* rp = (const float4*)(x + (size_t)row * 256);
        float4 a = rp[lane], c = rp[32 + lane];
        float vv[8] = {a.x, a.y, a.z, a.w, c.x, c.y, c.z, c.w};
        int id[8];
#pragma unroll
        for (int j = 0; j < 8; ++j) {
            int f = (j < 4) ? fa + j : fc + (j - 4);
            id[j] = uni ? bin_uni(vv[j]) : bin_gen(vv[j], bins + f * 33);
        }
        float s = 0.f;
#pragma unroll
        for (int j = 0; j < 8; ++j) {
            int f = (j < 4) ? fa + j : fc + (j - 4);
            s += __ldg(&W[f * 32 + id[j]]);
        }
        myIdx[lane]      = (unsigned)id[0] | ((unsigned)id[1] << 8)
                         | ((unsigned)id[2] << 16) | ((unsigned)id[3] << 24);
        myIdx[32 + lane] = (unsigned)id[4] | ((unsigned)id[5] << 8)
                         | ((unsigned)id[6] << 16) | ((unsigned)id[7] << 24);
        __syncwarp();
        if (lane < P) s += __ldg(&IW[lane * 1024 + ib[mpi] * 32 + ib[mpj]]);
        if (lane == 0)      atomicAdd(&sHist[id[0]], 1);
        else if (lane == 1) atomicAdd(&sHist[32 + id[1]], 1);
        s = warp_sum(s);
        if (lane == 0) out[row] = icpt + s;
    }
}

__global__ __launch_bounds__(THREADS, 1)
void fair_ebm_kernel(const float* __restrict__ x, const float* __restrict__ W,
                     const float* __restrict__ IW, const float* __restrict__ intercept,
                     const float* __restrict__ bins, const int* __restrict__ pair_i,
                     const int* __restrict__ pair_j, float* __restrict__ out,
                     int B, int P, int writeLoss)
{
    extern __shared__ float smem[];
    float* sIW2  = smem;                          // 32768: IW + W[2p][a] + W[2p+1][b]
    float* sWh   = sIW2 + 32768;                  // 6336: W rows 64..255, stride 33
    float* zeros = sWh + 6336;                    // 32
    float* sPart = zeros + 32;                    // NWARPS * MAXB * 36
    unsigned* sLog = (unsigned*)(sPart + NWARPS * MAXB * 36);  // NWARPS * 8 words
    int*   sHist = (int*)(sLog + NWARPS * 8);     // 64
    int*   sFlag = sHist + 64;                    // 2

    const int tid  = threadIdx.x;
    const int lane = tid & 31;
    const int warp = tid >> 5;
    const int TW   = gridDim.x * NWARPS;
    const int RPW  = (B + TW - 1) / TW;
    const int w    = blockIdx.x * NWARPS + warp;

    size_t row0 = (size_t)w * RPW;
    int nrt = 0;
    if (row0 < (size_t)B) {
        int rem = B - (int)row0;
        nrt = rem < RPW ? rem : RPW;
    }
    const int c3i = nrt - 1;
    const float4* xb = ((const float4*)x) + row0 * 64;

    // ---- ring preload (depth 2) before staging: ramp memory now ----
    float4 a0, c0, a1, c1;
    if (nrt > 0) {
        int r1 = 1 < c3i ? 1 : (c3i < 0 ? 0 : c3i);
        a0 = xb[lane];                   c0 = xb[32 + lane];
        a1 = xb[(size_t)r1 * 64 + lane]; c1 = xb[(size_t)r1 * 64 + 32 + lane];
    }

    if (tid == 0) { sFlag[0] = 1; sFlag[1] = 1; }
    if (tid < 64) sHist[tid] = 0;
    if (tid < 32) zeros[tid] = 0.0f;

    // ---- stage W rows 64..255 (bank-padded stride 33) ----
    {
        const float4* W4 = (const float4*)W;
        for (int i = tid; i < 1536; i += THREADS) {
            float4 v = W4[512 + i];
            int f = i * 4;
            float* d = sWh + (f >> 5) * 33 + (f & 31);
            d[0] = v.x; d[1] = v.y; d[2] = v.z; d[3] = v.w;
        }
    }
    // ---- verify uniform bins + identity pairs (P must be 32) ----
    {
        const float4* B4 = (const float4*)bins;
        bool bad = false;
        for (int i = tid; i < (256 * 33) / 4; i += THREADS) {
            float4 v = B4[i]; int e = i * 4;
            bad |= (v.x != (float)((e + 0) % 33) * 0.03125f);
            bad |= (v.y != (float)((e + 1) % 33) * 0.03125f);
            bad |= (v.z != (float)((e + 2) % 33) * 0.03125f);
            bad |= (v.w != (float)((e + 3) % 33) * 0.03125f);
        }
        if (bad) sFlag[0] = 0;
    }
    if (tid == 0 && P != 32) sFlag[1] = 0;
    if (tid < 32 && tid < P)
        if (pair_i[tid] != 2 * tid || pair_j[tid] != 2 * tid + 1) sFlag[1] = 0;
    __syncthreads();

    const bool fast = (sFlag[0] != 0) && (sFlag[1] != 0);

    if (fast) {
        // fold: sIW2[p][a][b] = IW[p][a][b] + W[2p][a] + W[2p+1][b]
        const float4* IW4 = (const float4*)IW;
        float4* D4 = (float4*)sIW2;
        for (int i = tid; i < 8192; i += THREADS) {
            float4 v = IW4[i];
            int e = i * 4;
            int p = e >> 10, a = (e >> 5) & 31, b = e & 31;
            float wa = __ldg(&W[(2 * p) * 32 + a]);
            float4 wb = __ldg((const float4*)&W[(2 * p + 1) * 32 + b]);
            v.x += wa + wb.x; v.y += wa + wb.y;
            v.z += wa + wb.z; v.w += wa + wb.w;
            D4[i] = v;
        }
    }
    __syncthreads();

    const float icpt = intercept[0];

    if (fast) {
        int h0 = 0, h5 = 0;
        if (nrt > 0) {
            // per-lane invariant lookup config (branch-free inner loop)
            const float *ub0, *ub1, *ub2, *ub3; int um, vm;
            if (lane < 16) {
                ub0 = sIW2 + (2 * lane) * 1024;
                ub1 = sIW2 + (2 * lane + 1) * 1024;
                ub2 = zeros; ub3 = zeros; um = 32; vm = 1;
            } else {
                int fr = 4 * lane - 64;
                ub0 = sWh + fr * 33;       ub1 = sWh + (fr + 2) * 33;
                ub2 = sWh + (fr + 1) * 33; ub3 = sWh + (fr + 3) * 33;
                um = 1; vm = 0;
            }
            const float* hb = sWh + (64 + 4 * lane) * 33;
            float* pbuf = sPart + warp * (MAXB * 36);
            unsigned char* logb = (unsigned char*)(sLog + warp * 8);  // 16+16 bytes

            for (int bb = 0; bb < nrt; bb += MAXB) {
                const int nr = (nrt - bb) < MAXB ? (nrt - bb) : MAXB;
                int r = 0;
                // (re)fill ring at batch start
                float4 A0, C0, A1, C1;
                if (bb == 0) { A0 = a0; C0 = c0; A1 = a1; C1 = c1; }
                else {
                    int rr0 = bb, rr1 = (bb + 1) <= c3i ? bb + 1 : c3i;
                    A0 = xb[(size_t)rr0 * 64 + lane]; C0 = xb[(size_t)rr0 * 64 + 32 + lane];
                    A1 = xb[(size_t)rr1 * 64 + lane]; C1 = xb[(size_t)rr1 * 64 + 32 + lane];
                }

                // process slot S (row bb+r), log bins, store partial, reload r+2
#define STEP(S) do {                                                          \
                    int p0 = bin_uni(A##S.x), p1 = bin_uni(A##S.y);           \
                    int p2 = bin_uni(A##S.z), p3 = bin_uni(A##S.w);           \
                    int p4 = bin_uni(C##S.x), p5 = bin_uni(C##S.y);           \
                    int p6 = bin_uni(C##S.z), p7 = bin_uni(C##S.w);           \
                    float s = ub0[p0 * um + p1 * vm]                          \
                            + ub1[p2 * um + p3 * vm]                          \
                            + ub2[p1] + ub3[p3]                               \
                            + hb[p4] + hb[33 + p5] + hb[66 + p6] + hb[99 + p7]; \
                    if (lane == 0)      logb[r]      = (unsigned char)p0;     \
                    else if (lane == 1) logb[16 + r] = (unsigned char)p1;     \
                    pbuf[r * 36 + lane] = s;                                  \
                    int rl_ = (bb + r + 2) <= c3i ? (bb + r + 2) : c3i;       \
                    const float4* xn_ = xb + (size_t)rl_ * 64;                \
                    A##S = xn_[lane]; C##S = xn_[32 + lane];                  \
                    ++r;                                                      \
                } while (0)

                const int nr2 = nr & ~1;
                while (r < nr2) { STEP(0); STEP(1); }
                if (nr & 1) STEP(0);
#undef STEP
                __syncwarp();
                // histogram from byte log: lane L counts occurrences of L
                for (int j = 0; j < nr; ++j) {
                    h0 += (logb[j] == lane);
                    h5 += (logb[16 + j] == lane);
                }
                // transpose flush: lane j sums the 32 partials of row j
                if (lane < nr) {
                    const float4* rp = (const float4*)(pbuf + lane * 36);
                    float4 t0 = rp[0], t1 = rp[1], t2 = rp[2], t3 = rp[3];
                    float4 t4 = rp[4], t5 = rp[5], t6 = rp[6], t7 = rp[7];
                    float u0 = (t0.x + t0.y) + (t0.z + t0.w);
                    float u1 = (t1.x + t1.y) + (t1.z + t1.w);
                    float u2 = (t2.x + t2.y) + (t2.z + t2.w);
                    float u3 = (t3.x + t3.y) + (t3.z + t3.w);
                    float u4 = (t4.x + t4.y) + (t4.z + t4.w);
                    float u5 = (t5.x + t5.y) + (t5.z + t5.w);
                    float u6 = (t6.x + t6.y) + (t6.z + t6.w);
                    float u7 = (t7.x + t7.y) + (t7.z + t7.w);
                    float tot = ((u0 + u1) + (u2 + u3)) + ((u4 + u5) + (u6 + u7));
                    out[row0 + bb + lane] = icpt + tot;
                }
                __syncwarp();
            }
        }
        // two spread-address atomics per warp, once
        atomicAdd(&sHist[lane], h0);
        atomicAdd(&sHist[32 + lane], h5);
    } else {
        unsigned* myIdx = (unsigned*)(sPart + warp * (MAXB * 36));
        slow_loop(x, out, W, IW, bins, pair_i, pair_j, myIdx, sHist,
                  lane, P, w, TW, B, icpt, sFlag[0] != 0);
    }

    // ---- cross-block reduce + last-block finalize ----
    __syncthreads();
    if (tid < 64) atomicAdd(&g_hist[tid], sHist[tid]);
    __threadfence();
    __syncthreads();

    __shared__ unsigned ticket;
    if (tid == 0) ticket = atomicAdd(&g_ctr, 1u);
    __syncthreads();

    if (ticket == gridDim.x - 1) {
        if (tid < 64) sHist[tid] = atomicAdd(&g_hist[tid], 0);
        __syncthreads();
        if (tid < 32) {
            const double invB = 1.0 / (double)B;
            double vsum = 0.0;
#pragma unroll
            for (int s2i = 0; s2i < 2; ++s2i) {
                const int f = s2i ? 5 : 0;
                double wv  = (double)W[f * NB + tid];
                double cnt = (double)sHist[s2i * 32 + tid];
                double t1 = cnt * wv;
                double t2 = t1 * wv;
#pragma unroll
                for (int off = 16; off > 0; off >>= 1) {
                    t1 += __shfl_xor_sync(0xffffffffu, t1, off);
                    t2 += __shfl_xor_sync(0xffffffffu, t2, off);
                }
                double mean = t1 * invB;
                vsum += t2 * invB - mean * mean;
            }
            if (tid == 0) {
                if (writeLoss) out[B] = (float)(0.1 * vsum);
                g_ctr = 0;
            }
        }
        if (tid < 64) g_hist[tid] = 0;
        __threadfence();
    }
}

extern "C" void kernel_launch(void* const* d_in, const int* in_sizes, int n_in,
                              void* d_out, int out_size)
{
    const float* x         = (const float*)d_in[0];
    const float* W         = (const float*)d_in[1];
    const float* IW        = (const float*)d_in[2];
    const float* intercept = (const float*)d_in[3];
    const float* bins      = (const float*)d_in[4];
    const int*   pair_i    = (const int*)d_in[5];
    const int*   pair_j    = (const int*)d_in[6];
    float*       out       = (float*)d_out;

    const int B = in_sizes[0] / 256;
    const int P = in_sizes[2] / 1024;
    const int writeLoss = (out_size > B) ? 1 : 0;

    int dev = 0;
    cudaGetDevice(&dev);
    int sms = 148;
    cudaDeviceGetAttribute(&sms, cudaDevAttrMultiProcessorCount, dev);

    const size_t shbytes =
        (size_t)(32768 + 6336 + 32 + NWARPS * MAXB * 36 + NWARPS * 8 + 64 + 2) * 4 + 32;
    cudaFuncSetAttribute(fair_ebm_kernel,
                         cudaFuncAttributeMaxDynamicSharedMemorySize, (int)shbytes);

    fair_ebm_kernel<<<sms, THREADS, shbytes>>>(x, W, IW, intercept, bins,
                                               pair_i, pair_j, out, B, P, writeLoss);
}